// round 11
// baseline (speedup 1.0000x reference)
#include <cuda_runtime.h>
#include <cuda_bf16.h>
#include <cstdint>

#define NUM_USERS 50000
#define NUM_ITEMS 40000
#define EMB 64
#define NNZ 2000000
#define BATCH 1024

// ---- scratch (static __device__ globals; no allocation allowed) ----
__device__ float         g_WqT[NUM_ITEMS * 128];     // Wq transposed: [item][128]
__device__ __nv_bfloat16 g_Wpb[NUM_ITEMS * EMB];     // Wp in bf16:   [item][64]
__device__ float         g_hsel[BATCH * 128];        // selected-user h accumulators
__device__ int           g_map[NUM_USERS];           // user -> batch slot (validated by back-check)
__device__ __nv_bfloat16 g_zb[BATCH * EMB];          // z in bf16
__device__ float         g_sexp[BATCH];
__device__ float         g_sdot[BATCH];
__device__ float         g_scnt[BATCH];
__device__ float         g_kl;

__device__ __forceinline__ unsigned pack_bf162(float lo, float hi) {
    __nv_bfloat162 t = __floats2bfloat162_rn(lo, hi);
    return *(unsigned*)&t;
}

// ---- 1: fused prep: Wq transpose + Wp->bf16 + zero scratch + user map ----
__global__ void __launch_bounds__(256)
k_prep(const float* __restrict__ Wq, const float* __restrict__ Wp,
       const int* __restrict__ user) {
    __shared__ float tile[32][33];
    int bid = blockIdx.x, tid = threadIdx.x;
    if (bid < 5000) {
        int i0 = (bid % 1250) * 32, k0 = (bid / 1250) * 32;
        int tx = tid & 31, ty = tid >> 5;          // (32,8)
#pragma unroll
        for (int r = 0; r < 32; r += 8)
            tile[ty + r][tx] = Wq[(size_t)(k0 + ty + r) * NUM_ITEMS + i0 + tx];
        __syncthreads();
#pragma unroll
        for (int r = 0; r < 32; r += 8)
            g_WqT[(size_t)(i0 + ty + r) * 128 + k0 + tx] = tile[tx][ty + r];
    } else if (bid < 6250) {
        int i = (bid - 5000) * 256 + tid;          // < 320000 exactly
        const float4* in4 = (const float4*)Wp;
        float4 a = in4[2 * i], b = in4[2 * i + 1];
        uint4 o;
        o.x = pack_bf162(a.x, a.y);
        o.y = pack_bf162(a.z, a.w);
        o.z = pack_bf162(b.x, b.y);
        o.w = pack_bf162(b.z, b.w);
        ((uint4*)g_Wpb)[i] = o;
    } else if (bid < 6762) {
        int i = (bid - 6250) * 256 + tid;          // < 131072 exactly
        g_hsel[i] = 0.f;
    } else {
#pragma unroll
        for (int b = tid; b < BATCH; b += 256) {
            g_sexp[b] = 0.f; g_sdot[b] = 0.f; g_scnt[b] = 0.f;
            g_map[user[b]] = b;                    // racing store; any winner valid
        }
        if (tid == 0) g_kl = 0.f;
    }
}

// ---- 2: scatter kept edges (warp-ballot compaction; map validated by back-check) ----
__global__ void k_edges(const float* __restrict__ vals,
                        const int* __restrict__ rows,
                        const int* __restrict__ cols,
                        const int* __restrict__ user) {
    int idx  = blockIdx.x * blockDim.x + threadIdx.x;
    int lane = threadIdx.x & 31;
    int slot = -1, col = 0;
    float val = 0.f;
    if (idx < NNZ) {
        int r = rows[idx];
        int s = g_map[r];
        if ((unsigned)s < BATCH && __ldg(&user[s]) == r) slot = s;
        col = cols[idx];
        val = vals[idx];
    }
    unsigned m = __ballot_sync(0xFFFFFFFFu, slot >= 0);
    while (m) {
        int j = __ffs(m) - 1; m &= m - 1;
        int   c = __shfl_sync(0xFFFFFFFFu, col, j);
        float v = __shfl_sync(0xFFFFFFFFu, val, j);
        int   s = __shfl_sync(0xFFFFFFFFu, slot, j);
        const float* wr = &g_WqT[(size_t)c * 128];
        float* hr = &g_hsel[s * 128];
#pragma unroll
        for (int k = lane; k < 128; k += 32)
            atomicAdd(&hr[k], v * wr[k]);
    }
}

// ---- 3: reparameterize + KL ----
__global__ void k_z(const float* __restrict__ bq,
                    const float* __restrict__ eps,
                    const int* __restrict__ user) {
    int b = blockIdx.x, k = threadIdx.x;   // 64 threads
    int u = user[b];
    int s = g_map[u];
    float mu = g_hsel[s * 128 + k]      + bq[k];
    float lv = g_hsel[s * 128 + 64 + k] + bq[64 + k];
    float z  = mu + eps[u * EMB + k] * __expf(0.5f * lv);
    g_zb[b * EMB + k] = __float2bfloat16(z);
    float t = 1.f + lv - mu * mu - __expf(lv);
#pragma unroll
    for (int o = 16; o > 0; o >>= 1) t += __shfl_down_sync(0xFFFFFFFFu, t, o);
    __shared__ float sm[2];
    if ((threadIdx.x & 31) == 0) sm[threadIdx.x >> 5] = t;
    __syncthreads();
    if (threadIdx.x == 0) atomicAdd(&g_kl, sm[0] + sm[1]);
}

// ---- 4: fused decoder GEMM (bf16 HMMA) + softmax-stats epilogue ----
// x streamed via column-grouped cp.async 4-slot ring (32KB in flight/CTA),
// consumed per nf stage directly as raw floats; Wp tile XOR-swizzled in smem.
__device__ __forceinline__ void mma16816(float* d, const unsigned* a, const unsigned* b) {
    asm volatile(
        "mma.sync.aligned.m16n8k16.row.col.f32.bf16.bf16.f32 "
        "{%0,%1,%2,%3}, {%4,%5,%6,%7}, {%8,%9}, {%0,%1,%2,%3};\n"
        : "+f"(d[0]), "+f"(d[1]), "+f"(d[2]), "+f"(d[3])
        : "r"(a[0]), "r"(a[1]), "r"(a[2]), "r"(a[3]), "r"(b[0]), "r"(b[1]));
}

__device__ __forceinline__ void cp_async16(void* smem_dst, const void* gsrc, int src_bytes) {
    unsigned saddr = (unsigned)__cvta_generic_to_shared(smem_dst);
    asm volatile("cp.async.cg.shared.global [%0], [%1], 16, %2;\n"
                 :: "r"(saddr), "l"(gsrc), "r"(src_bytes));
}
__device__ __forceinline__ void cp_commit() {
    asm volatile("cp.async.commit_group;\n" ::: "memory");
}
template <int N>
__device__ __forceinline__ void cp_wait() {
    asm volatile("cp.async.wait_group %0;\n" :: "n"(N) : "memory");
}

__global__ void __launch_bounds__(256, 3)
k_gemm(const float* __restrict__ bp, const float* __restrict__ x) {
    __shared__ __align__(16) unsigned char sWp[128 * 128];   // 16 KB, XOR-swizzled
    __shared__ __align__(16) float sXr[4][128 * 16];         // 32 KB, 4-slot x ring

    int tid = threadIdx.x;
    int w = tid >> 5, lane = tid & 31;
    int wm = w & 3, wn = w >> 2;                 // 4 warps along M, 2 along N
    int m_blk  = blockIdx.y * 128;
    int m_base = m_blk + wm * 32;                // batch rows (in-range)
    int n_blk  = blockIdx.x * 128;
    int n_base = n_blk + wn * 64;                // item cols (tail-predicated)
    int g = lane >> 2, tg = lane & 3;

    // group G covers cols {n_blk+G*8..+7} and {n_blk+64+G*8..+7}, all 128 rows;
    // smem slot layout: [row][16 floats] = [segA 8 | segB 8]
#define ISSUE_X(G) do {                                                         \
        _Pragma("unroll")                                                       \
        for (int it = 0; it < 2; it++) {                                        \
            int idx  = it * 256 + tid;           /* 0..511 */                   \
            int row  = idx >> 2;                 /* 0..127 */                   \
            int half = (idx >> 1) & 1;           /* 0=segA, 1=segB */           \
            int q    = idx & 1;                  /* which 16B of the 32B */     \
            int gcol = n_blk + half * 64 + (G) * 8 + q * 4;                     \
            int ok   = (gcol + 3 < NUM_ITEMS) ? 16 : 0;                         \
            cp_async16(&sXr[(G) & 3][row * 16 + half * 8 + q * 4],              \
                       &x[(size_t)(m_blk + row) * NUM_ITEMS + gcol], ok);       \
        }                                                                       \
        cp_commit();                                                            \
    } while (0)

    ISSUE_X(0); ISSUE_X(1); ISSUE_X(2); ISSUE_X(3);

    // ---- fill swizzled sWp tile: rows n_blk..n_blk+127 ----
#pragma unroll
    for (int it = 0; it < 4; it++) {
        int i = it * 256 + tid;                  // 0..1023
        int row = i >> 3, off = i & 7;
        int gr = n_blk + row;
        uint4 v = make_uint4(0u, 0u, 0u, 0u);
        if (gr < NUM_ITEMS) v = *(const uint4*)&g_Wpb[(size_t)gr * 64 + off * 8];
        *(uint4*)&sWp[row * 128 + ((off ^ (row & 7)) * 16)] = v;
    }

    // ---- A fragments: z tile 32(M) x 64(K), register-resident ----
    unsigned a[2][4][4];
#pragma unroll
    for (int mf = 0; mf < 2; mf++) {
        int r0 = m_base + mf * 16 + g;
#pragma unroll
        for (int kf = 0; kf < 4; kf++) {
            int kb = kf * 16 + tg * 2;
            a[mf][kf][0] = *(const unsigned*)&g_zb[(r0)     * 64 + kb];
            a[mf][kf][1] = *(const unsigned*)&g_zb[(r0 + 8) * 64 + kb];
            a[mf][kf][2] = *(const unsigned*)&g_zb[(r0)     * 64 + kb + 8];
            a[mf][kf][3] = *(const unsigned*)&g_zb[(r0 + 8) * 64 + kb + 8];
        }
    }

    float sexp[4] = {0, 0, 0, 0}, sdot[4] = {0, 0, 0, 0}, scnt[4] = {0, 0, 0, 0};

#pragma unroll
    for (int nf = 0; nf < 8; nf++) {
        // wait for group nf: pending allowed = 3 (stages 0-4), then 7-nf
        switch (nf) {
            case 5:  cp_wait<2>(); break;
            case 6:  cp_wait<1>(); break;
            case 7:  cp_wait<0>(); break;
            default: cp_wait<3>(); break;
        }
        __syncthreads();                          // x slot + (first iter) sWp visible

        // B fragments from swizzled smem (conflict-free LDS)
        int rloc = wn * 64 + nf * 8 + g;          // local smem Wp row; rloc&7 == g
        unsigned bf[4][2];
#pragma unroll
        for (int kf = 0; kf < 4; kf++) {
            bf[kf][0] = *(const unsigned*)&sWp[rloc * 128 + (((kf * 2)     ^ g) * 16) + tg * 4];
            bf[kf][1] = *(const unsigned*)&sWp[rloc * 128 + (((kf * 2 + 1) ^ g) * 16) + tg * 4];
        }

        float d[2][4] = {{0, 0, 0, 0}, {0, 0, 0, 0}};
#pragma unroll
        for (int mf = 0; mf < 2; mf++)
#pragma unroll
            for (int kf = 0; kf < 4; kf++)
                mma16816(d[mf], a[mf][kf], bf[kf]);

        int c0 = n_base + nf * 8 + tg * 2;
        const float* slot = sXr[nf & 3];
        if (c0 < NUM_ITEMS) {
            float2 bpv = *(const float2*)&bp[c0];
#pragma unroll
            for (int mf = 0; mf < 2; mf++)
#pragma unroll
                for (int h = 0; h < 2; h++) {
                    int li = mf * 2 + h;
                    int lrow = wm * 32 + mf * 16 + h * 8 + g;
                    float2 xv = *(const float2*)&slot[lrow * 16 + wn * 8 + tg * 2];
                    float v0f = d[mf][h * 2 + 0] + bpv.x;
                    float v1f = d[mf][h * 2 + 1] + bpv.y;
                    sexp[li] += __expf(v0f) + __expf(v1f);
                    sdot[li] += xv.x * v0f + xv.y * v1f;
                    scnt[li] += xv.x + xv.y;
                }
        }
        __syncthreads();                          // all reads of slot nf&3 done
        if (nf < 4) {                             // refill freed slot with group nf+4
            switch (nf) {
                case 0:  ISSUE_X(4); break;
                case 1:  ISSUE_X(5); break;
                case 2:  ISSUE_X(6); break;
                default: ISSUE_X(7); break;
            }
        }
    }
#undef ISSUE_X

    // reduce across the 4 threads of each group (tg), then atomics per row
#pragma unroll
    for (int li = 0; li < 4; li++) {
        float se = sexp[li], sd = sdot[li], sc = scnt[li];
#pragma unroll
        for (int o = 1; o < 4; o <<= 1) {
            se += __shfl_xor_sync(0xFFFFFFFFu, se, o);
            sd += __shfl_xor_sync(0xFFFFFFFFu, sd, o);
            sc += __shfl_xor_sync(0xFFFFFFFFu, sc, o);
        }
        if (tg == 0) {
            int row = m_base + (li >> 1) * 16 + (li & 1) * 8 + g;
            atomicAdd(&g_sexp[row], se);
            atomicAdd(&g_sdot[row], sd);
            atomicAdd(&g_scnt[row], sc);
        }
    }
}

// ---- 5: final reduction ----
__global__ void k_final(float* __restrict__ out) {
    __shared__ float sm[256];
    float acc = 0.f;
    for (int r = threadIdx.x; r < BATCH; r += 256)
        acc += g_scnt[r] * logf(g_sexp[r]) - g_sdot[r];
    sm[threadIdx.x] = acc;
    __syncthreads();
    for (int o = 128; o > 0; o >>= 1) {
        if (threadIdx.x < o) sm[threadIdx.x] += sm[threadIdx.x + o];
        __syncthreads();
    }
    if (threadIdx.x == 0) {
        out[0] = sm[0] / (float)BATCH;
        out[1] = -0.5f * g_kl / (float)BATCH;
    }
}

extern "C" void kernel_launch(void* const* d_in, const int* in_sizes, int n_in,
                              void* d_out, int out_size) {
    const float* graph_vals = (const float*)d_in[0];
    const float* Wq         = (const float*)d_in[1];
    const float* bq         = (const float*)d_in[2];
    const float* Wp         = (const float*)d_in[3];
    const float* bp         = (const float*)d_in[4];
    const float* x          = (const float*)d_in[5];
    const float* eps        = (const float*)d_in[6];
    const int*   graph_rows = (const int*)d_in[7];
    const int*   graph_cols = (const int*)d_in[8];
    const int*   user       = (const int*)d_in[9];
    float* out = (float*)d_out;

    k_prep<<<6763, 256>>>(Wq, Wp, user);
    k_edges<<<(NNZ + 255) / 256, 256>>>(graph_vals, graph_rows, graph_cols, user);
    k_z<<<BATCH, 64>>>(bq, eps, user);
    {
        dim3 grid((NUM_ITEMS + 127) / 128, BATCH / 128);
        k_gemm<<<grid, 256>>>(bp, x);
    }
    k_final<<<1, 256>>>(out);
}

// round 12
// speedup vs baseline: 1.0021x; 1.0021x over previous
#include <cuda_runtime.h>
#include <cuda_bf16.h>
#include <cstdint>

#define NUM_USERS 50000
#define NUM_ITEMS 40000
#define EMB 64
#define NNZ 2000000
#define BATCH 1024

// ---- scratch (static __device__ globals; no allocation allowed) ----
__device__ float         g_WqT[NUM_ITEMS * 128];     // Wq transposed: [item][128]
__device__ __nv_bfloat16 g_Wpb[NUM_ITEMS * EMB];     // Wp in bf16:   [item][64]
__device__ float         g_hsel[BATCH * 128];        // selected-user h accumulators
__device__ int           g_map[NUM_USERS];           // user -> batch slot (validated by back-check)
__device__ __nv_bfloat16 g_zb[BATCH * EMB];          // z in bf16
__device__ float         g_sexp[BATCH];
__device__ float         g_sdot[BATCH];
__device__ float         g_scnt[BATCH];
__device__ float         g_kl;

__device__ __forceinline__ unsigned pack_bf162(float lo, float hi) {
    __nv_bfloat162 t = __floats2bfloat162_rn(lo, hi);
    return *(unsigned*)&t;
}

// ---- 1: fused prep: Wq transpose + Wp->bf16 + zero scratch + user map ----
__global__ void __launch_bounds__(256)
k_prep(const float* __restrict__ Wq, const float* __restrict__ Wp,
       const int* __restrict__ user) {
    __shared__ float tile[32][33];
    int bid = blockIdx.x, tid = threadIdx.x;
    if (bid < 5000) {
        int i0 = (bid % 1250) * 32, k0 = (bid / 1250) * 32;
        int tx = tid & 31, ty = tid >> 5;          // (32,8)
#pragma unroll
        for (int r = 0; r < 32; r += 8)
            tile[ty + r][tx] = Wq[(size_t)(k0 + ty + r) * NUM_ITEMS + i0 + tx];
        __syncthreads();
#pragma unroll
        for (int r = 0; r < 32; r += 8)
            g_WqT[(size_t)(i0 + ty + r) * 128 + k0 + tx] = tile[tx][ty + r];
    } else if (bid < 6250) {
        int i = (bid - 5000) * 256 + tid;          // < 320000 exactly
        const float4* in4 = (const float4*)Wp;
        float4 a = in4[2 * i], b = in4[2 * i + 1];
        uint4 o;
        o.x = pack_bf162(a.x, a.y);
        o.y = pack_bf162(a.z, a.w);
        o.z = pack_bf162(b.x, b.y);
        o.w = pack_bf162(b.z, b.w);
        ((uint4*)g_Wpb)[i] = o;
    } else if (bid < 6762) {
        int i = (bid - 6250) * 256 + tid;          // < 131072 exactly
        g_hsel[i] = 0.f;
    } else {
#pragma unroll
        for (int b = tid; b < BATCH; b += 256) {
            g_sexp[b] = 0.f; g_sdot[b] = 0.f; g_scnt[b] = 0.f;
            g_map[user[b]] = b;                    // racing store; any winner valid
        }
        if (tid == 0) g_kl = 0.f;
    }
}

// ---- 2: scatter kept edges (warp-ballot compaction; map validated by back-check) ----
__global__ void k_edges(const float* __restrict__ vals,
                        const int* __restrict__ rows,
                        const int* __restrict__ cols,
                        const int* __restrict__ user) {
    int idx  = blockIdx.x * blockDim.x + threadIdx.x;
    int lane = threadIdx.x & 31;
    int slot = -1, col = 0;
    float val = 0.f;
    if (idx < NNZ) {
        int r = rows[idx];
        int s = g_map[r];
        if ((unsigned)s < BATCH && __ldg(&user[s]) == r) slot = s;
        col = cols[idx];
        val = vals[idx];
    }
    unsigned m = __ballot_sync(0xFFFFFFFFu, slot >= 0);
    while (m) {
        int j = __ffs(m) - 1; m &= m - 1;
        int   c = __shfl_sync(0xFFFFFFFFu, col, j);
        float v = __shfl_sync(0xFFFFFFFFu, val, j);
        int   s = __shfl_sync(0xFFFFFFFFu, slot, j);
        const float* wr = &g_WqT[(size_t)c * 128];
        float* hr = &g_hsel[s * 128];
#pragma unroll
        for (int k = lane; k < 128; k += 32)
            atomicAdd(&hr[k], v * wr[k]);
    }
}

// ---- 3: reparameterize + KL ----
__global__ void k_z(const float* __restrict__ bq,
                    const float* __restrict__ eps,
                    const int* __restrict__ user) {
    int b = blockIdx.x, k = threadIdx.x;   // 64 threads
    int u = user[b];
    int s = g_map[u];
    float mu = g_hsel[s * 128 + k]      + bq[k];
    float lv = g_hsel[s * 128 + 64 + k] + bq[64 + k];
    float z  = mu + eps[u * EMB + k] * __expf(0.5f * lv);
    g_zb[b * EMB + k] = __float2bfloat16(z);
    float t = 1.f + lv - mu * mu - __expf(lv);
#pragma unroll
    for (int o = 16; o > 0; o >>= 1) t += __shfl_down_sync(0xFFFFFFFFu, t, o);
    __shared__ float sm[2];
    if ((threadIdx.x & 31) == 0) sm[threadIdx.x >> 5] = t;
    __syncthreads();
    if (threadIdx.x == 0) atomicAdd(&g_kl, sm[0] + sm[1]);
}

// ---- 4: fused decoder GEMM (bf16 HMMA) + softmax-stats epilogue ----
// Entire 64KB x tile issued as ONE cp.async batch at block start (deep MLP,
// drain hidden under Wp/A loads), single wait+barrier, raw-float epilogue.
__device__ __forceinline__ void mma16816(float* d, const unsigned* a, const unsigned* b) {
    asm volatile(
        "mma.sync.aligned.m16n8k16.row.col.f32.bf16.bf16.f32 "
        "{%0,%1,%2,%3}, {%4,%5,%6,%7}, {%8,%9}, {%0,%1,%2,%3};\n"
        : "+f"(d[0]), "+f"(d[1]), "+f"(d[2]), "+f"(d[3])
        : "r"(a[0]), "r"(a[1]), "r"(a[2]), "r"(a[3]), "r"(b[0]), "r"(b[1]));
}

__device__ __forceinline__ void cp_async16(void* smem_dst, const void* gsrc, int src_bytes) {
    unsigned saddr = (unsigned)__cvta_generic_to_shared(smem_dst);
    asm volatile("cp.async.cg.shared.global [%0], [%1], 16, %2;\n"
                 :: "r"(saddr), "l"(gsrc), "r"(src_bytes));
}
__device__ __forceinline__ void cp_commit() {
    asm volatile("cp.async.commit_group;\n" ::: "memory");
}
template <int N>
__device__ __forceinline__ void cp_wait() {
    asm volatile("cp.async.wait_group %0;\n" :: "n"(N) : "memory");
}

#define WP_STRIDE 144                 // bytes per smem Wp row (conflict-free)
#define X_STRIDE  132                 // floats per smem x row (528 B; <=2-way)
#define GEMM_SMEM (128 * WP_STRIDE + 128 * X_STRIDE * 4)   // 18432 + 67584 = 86016 B

__global__ void __launch_bounds__(256, 2)
k_gemm(const float* __restrict__ bp, const float* __restrict__ x) {
    extern __shared__ __align__(16) unsigned char smem_dyn[];
    unsigned char* sWp = smem_dyn;                          // 18 KB
    float* sXf = (float*)(smem_dyn + 128 * WP_STRIDE);      // 66 KB

    int tid = threadIdx.x;
    int w = tid >> 5, lane = tid & 31;
    int wm = w & 3, wn = w >> 2;                 // 4 warps along M, 2 along N
    int m_blk  = blockIdx.y * 128;
    int m_base = m_blk + wm * 32;                // batch rows (in-range)
    int n_blk  = blockIdx.x * 128;
    int n_base = n_blk + wn * 64;                // item cols (tail-predicated)
    int g = lane >> 2, tg = lane & 3;

    // ---- issue the ENTIRE x tile (128 rows x 512B) as cp.async, one commit ----
#pragma unroll
    for (int it = 0; it < 16; it++) {
        int idx = it * 256 + tid;                // 0..4095 float4 slots
        int row = idx >> 5, seg = idx & 31;      // row 0..127, seg 0..31 (16B each)
        int gcol = n_blk + seg * 4;
        int ok = (gcol + 3 < NUM_ITEMS) ? 16 : 0;
        cp_async16(&sXf[row * X_STRIDE + seg * 4],
                   &x[(size_t)(m_blk + row) * NUM_ITEMS + gcol], ok);
    }
    cp_commit();

    // ---- fill smem Wpb tile: rows n_blk..n_blk+127 (hides cp.async drain) ----
#pragma unroll
    for (int it = 0; it < 4; it++) {
        int i = it * 256 + tid;                  // 0..1023
        int row = i >> 3, off = i & 7;
        int gr = n_blk + row;
        uint4 v = make_uint4(0u, 0u, 0u, 0u);
        if (gr < NUM_ITEMS) v = *(const uint4*)&g_Wpb[(size_t)gr * 64 + off * 8];
        *(uint4*)&sWp[row * WP_STRIDE + off * 16] = v;
    }

    // ---- A fragments: z tile 32(M) x 64(K), register-resident ----
    unsigned a[2][4][4];
#pragma unroll
    for (int mf = 0; mf < 2; mf++) {
        int r0 = m_base + mf * 16 + g;
#pragma unroll
        for (int kf = 0; kf < 4; kf++) {
            int kb = kf * 16 + tg * 2;
            a[mf][kf][0] = *(const unsigned*)&g_zb[(r0)     * 64 + kb];
            a[mf][kf][1] = *(const unsigned*)&g_zb[(r0 + 8) * 64 + kb];
            a[mf][kf][2] = *(const unsigned*)&g_zb[(r0)     * 64 + kb + 8];
            a[mf][kf][3] = *(const unsigned*)&g_zb[(r0 + 8) * 64 + kb + 8];
        }
    }

    cp_wait<0>();
    __syncthreads();                             // ONE barrier: x + Wp visible

    float sexp[4] = {0, 0, 0, 0}, sdot[4] = {0, 0, 0, 0}, scnt[4] = {0, 0, 0, 0};

#pragma unroll
    for (int nf = 0; nf < 8; nf++) {
        // B fragments from smem (conflict-free LDS)
        int rloc = wn * 64 + nf * 8 + g;         // local smem Wp row
        unsigned bf[4][2];
#pragma unroll
        for (int kf = 0; kf < 4; kf++) {
            bf[kf][0] = *(const unsigned*)&sWp[rloc * WP_STRIDE + kf * 32 + tg * 4];
            bf[kf][1] = *(const unsigned*)&sWp[rloc * WP_STRIDE + kf * 32 + tg * 4 + 16];
        }

        float d[2][4] = {{0, 0, 0, 0}, {0, 0, 0, 0}};
#pragma unroll
        for (int mf = 0; mf < 2; mf++)
#pragma unroll
            for (int kf = 0; kf < 4; kf++)
                mma16816(d[mf], a[mf][kf], bf[kf]);

        int c0 = n_base + nf * 8 + tg * 2;
        int xoff = wn * 64 + nf * 8 + tg * 2;    // col offset within smem x row
        if (c0 < NUM_ITEMS) {
            float2 bpv = *(const float2*)&bp[c0];
#pragma unroll
            for (int mf = 0; mf < 2; mf++)
#pragma unroll
                for (int h = 0; h < 2; h++) {
                    int li = mf * 2 + h;
                    int lrow = wm * 32 + mf * 16 + h * 8 + g;
                    float2 xv = *(const float2*)&sXf[lrow * X_STRIDE + xoff];
                    float v0f = d[mf][h * 2 + 0] + bpv.x;
                    float v1f = d[mf][h * 2 + 1] + bpv.y;
                    sexp[li] += __expf(v0f) + __expf(v1f);
                    sdot[li] += xv.x * v0f + xv.y * v1f;
                    scnt[li] += xv.x + xv.y;
                }
        }
    }

    // reduce across the 4 threads of each group (tg), then atomics per row
#pragma unroll
    for (int li = 0; li < 4; li++) {
        float se = sexp[li], sd = sdot[li], sc = scnt[li];
#pragma unroll
        for (int o = 1; o < 4; o <<= 1) {
            se += __shfl_xor_sync(0xFFFFFFFFu, se, o);
            sd += __shfl_xor_sync(0xFFFFFFFFu, sd, o);
            sc += __shfl_xor_sync(0xFFFFFFFFu, sc, o);
        }
        if (tg == 0) {
            int row = m_base + (li >> 1) * 16 + (li & 1) * 8 + g;
            atomicAdd(&g_sexp[row], se);
            atomicAdd(&g_sdot[row], sd);
            atomicAdd(&g_scnt[row], sc);
        }
    }
}

// ---- 5: final reduction ----
__global__ void k_final(float* __restrict__ out) {
    __shared__ float sm[256];
    float acc = 0.f;
    for (int r = threadIdx.x; r < BATCH; r += 256)
        acc += g_scnt[r] * logf(g_sexp[r]) - g_sdot[r];
    sm[threadIdx.x] = acc;
    __syncthreads();
    for (int o = 128; o > 0; o >>= 1) {
        if (threadIdx.x < o) sm[threadIdx.x] += sm[threadIdx.x + o];
        __syncthreads();
    }
    if (threadIdx.x == 0) {
        out[0] = sm[0] / (float)BATCH;
        out[1] = -0.5f * g_kl / (float)BATCH;
    }
}

extern "C" void kernel_launch(void* const* d_in, const int* in_sizes, int n_in,
                              void* d_out, int out_size) {
    const float* graph_vals = (const float*)d_in[0];
    const float* Wq         = (const float*)d_in[1];
    const float* bq         = (const float*)d_in[2];
    const float* Wp         = (const float*)d_in[3];
    const float* bp         = (const float*)d_in[4];
    const float* x          = (const float*)d_in[5];
    const float* eps        = (const float*)d_in[6];
    const int*   graph_rows = (const int*)d_in[7];
    const int*   graph_cols = (const int*)d_in[8];
    const int*   user       = (const int*)d_in[9];
    float* out = (float*)d_out;

    cudaFuncSetAttribute(k_gemm, cudaFuncAttributeMaxDynamicSharedMemorySize, GEMM_SMEM);

    k_prep<<<6763, 256>>>(Wq, Wp, user);
    k_edges<<<(NNZ + 255) / 256, 256>>>(graph_vals, graph_rows, graph_cols, user);
    k_z<<<BATCH, 64>>>(bq, eps, user);
    {
        dim3 grid((NUM_ITEMS + 127) / 128, BATCH / 128);
        k_gemm<<<grid, 256, GEMM_SMEM>>>(bp, x);
    }
    k_final<<<1, 256>>>(out);
}

// round 13
// speedup vs baseline: 1.1375x; 1.1351x over previous
#include <cuda_runtime.h>
#include <cuda_bf16.h>
#include <cstdint>

#define NUM_USERS 50000
#define NUM_ITEMS 40000
#define EMB 64
#define NNZ 2000000
#define BATCH 1024

// ---- scratch (static __device__ globals; no allocation allowed) ----
__device__ float         g_WqT[NUM_ITEMS * 128];     // Wq transposed: [item][128]
__device__ __nv_bfloat16 g_Wpb[NUM_ITEMS * EMB];     // Wp in bf16:   [item][64]
__device__ float         g_ebp[NUM_ITEMS];           // exp(bp)
__device__ float         g_hsel[BATCH * 128];        // selected-user h accumulators
__device__ int           g_map[NUM_USERS];           // user -> batch slot (validated by back-check)
__device__ __nv_bfloat16 g_zb[BATCH * EMB];          // z in bf16
__device__ float         g_sexp[BATCH];
__device__ float         g_sdot[BATCH];
__device__ float         g_scnt[BATCH];
__device__ float         g_kl;

__device__ __forceinline__ unsigned pack_bf162(float lo, float hi) {
    __nv_bfloat162 t = __floats2bfloat162_rn(lo, hi);
    return *(unsigned*)&t;
}

// ---- 1: fused prep: Wq transpose + Wp->bf16 + exp(bp) + zero scratch + map ----
// regions: [0,5000) transpose | [5000,6250) wpcvt | [6250,6762) hsel zero |
//          [6762] misc | [6763,6920) ebp
__global__ void __launch_bounds__(256)
k_prep(const float* __restrict__ Wq, const float* __restrict__ Wp,
       const float* __restrict__ bp, const int* __restrict__ user) {
    __shared__ float tile[32][33];
    int bid = blockIdx.x, tid = threadIdx.x;
    if (bid < 5000) {
        int i0 = (bid % 1250) * 32, k0 = (bid / 1250) * 32;
        int tx = tid & 31, ty = tid >> 5;          // (32,8)
#pragma unroll
        for (int r = 0; r < 32; r += 8)
            tile[ty + r][tx] = Wq[(size_t)(k0 + ty + r) * NUM_ITEMS + i0 + tx];
        __syncthreads();
#pragma unroll
        for (int r = 0; r < 32; r += 8)
            g_WqT[(size_t)(i0 + ty + r) * 128 + k0 + tx] = tile[tx][ty + r];
    } else if (bid < 6250) {
        int i = (bid - 5000) * 256 + tid;          // < 320000 exactly
        const float4* in4 = (const float4*)Wp;
        float4 a = in4[2 * i], b = in4[2 * i + 1];
        uint4 o;
        o.x = pack_bf162(a.x, a.y);
        o.y = pack_bf162(a.z, a.w);
        o.z = pack_bf162(b.x, b.y);
        o.w = pack_bf162(b.z, b.w);
        ((uint4*)g_Wpb)[i] = o;
    } else if (bid < 6762) {
        int i = (bid - 6250) * 256 + tid;          // < 131072 exactly
        g_hsel[i] = 0.f;
    } else if (bid == 6762) {
#pragma unroll
        for (int b = tid; b < BATCH; b += 256) {
            g_sexp[b] = 0.f; g_sdot[b] = 0.f; g_scnt[b] = 0.f;
            g_map[user[b]] = b;                    // racing store; any winner valid
        }
        if (tid == 0) g_kl = 0.f;
    } else {
        int i = (bid - 6763) * 256 + tid;
        if (i < NUM_ITEMS) g_ebp[i] = __expf(bp[i]);
    }
}

// ---- 2: scatter kept edges (warp-ballot compaction; map validated by back-check) ----
__global__ void k_edges(const float* __restrict__ vals,
                        const int* __restrict__ rows,
                        const int* __restrict__ cols,
                        const int* __restrict__ user) {
    int idx  = blockIdx.x * blockDim.x + threadIdx.x;
    int lane = threadIdx.x & 31;
    int slot = -1, col = 0;
    float val = 0.f;
    if (idx < NNZ) {
        int r = rows[idx];
        int s = g_map[r];
        if ((unsigned)s < BATCH && __ldg(&user[s]) == r) slot = s;
        col = cols[idx];
        val = vals[idx];
    }
    unsigned m = __ballot_sync(0xFFFFFFFFu, slot >= 0);
    while (m) {
        int j = __ffs(m) - 1; m &= m - 1;
        int   c = __shfl_sync(0xFFFFFFFFu, col, j);
        float v = __shfl_sync(0xFFFFFFFFu, val, j);
        int   s = __shfl_sync(0xFFFFFFFFu, slot, j);
        const float* wr = &g_WqT[(size_t)c * 128];
        float* hr = &g_hsel[s * 128];
#pragma unroll
        for (int k = lane; k < 128; k += 32)
            atomicAdd(&hr[k], v * wr[k]);
    }
}

// ---- 3: reparameterize + KL ----
__global__ void k_z(const float* __restrict__ bq,
                    const float* __restrict__ eps,
                    const int* __restrict__ user) {
    int b = blockIdx.x, k = threadIdx.x;   // 64 threads
    int u = user[b];
    int s = g_map[u];
    float mu = g_hsel[s * 128 + k]      + bq[k];
    float lv = g_hsel[s * 128 + 64 + k] + bq[64 + k];
    float z  = mu + eps[u * EMB + k] * __expf(0.5f * lv);
    g_zb[b * EMB + k] = __float2bfloat16(z);
    float t = 1.f + lv - mu * mu - __expf(lv);
#pragma unroll
    for (int o = 16; o > 0; o >>= 1) t += __shfl_down_sync(0xFFFFFFFFu, t, o);
    __shared__ float sm[2];
    if ((threadIdx.x & 31) == 0) sm[threadIdx.x >> 5] = t;
    __syncthreads();
    if (threadIdx.x == 0) atomicAdd(&g_kl, sm[0] + sm[1]);
}

// ---- 4: fused decoder GEMM (bf16 HMMA) + thinned softmax-stats epilogue ----
// scnt via popcount at block end; bp folded out via precomputed exp(bp);
// sdot bp-part recovered by per-row set-bit walk at block end.
__device__ __forceinline__ void mma16816(float* d, const unsigned* a, const unsigned* b) {
    asm volatile(
        "mma.sync.aligned.m16n8k16.row.col.f32.bf16.bf16.f32 "
        "{%0,%1,%2,%3}, {%4,%5,%6,%7}, {%8,%9}, {%0,%1,%2,%3};\n"
        : "+f"(d[0]), "+f"(d[1]), "+f"(d[2]), "+f"(d[3])
        : "r"(a[0]), "r"(a[1]), "r"(a[2]), "r"(a[3]), "r"(b[0]), "r"(b[1]));
}

#define WP_STRIDE 144   // bytes per smem row: 128 data + 16 pad (bank-conflict-free)

__global__ void __launch_bounds__(256, 3)
k_gemm(const float* __restrict__ bp, const float* __restrict__ x) {
    __shared__ __align__(16) unsigned char sWp[128 * WP_STRIDE];   // 18 KB
    __shared__ __align__(16) unsigned sX[128 * 4];                 // 2 KB bitmask

    int tid = threadIdx.x;
    int w = tid >> 5, lane = tid & 31;
    int wm = w & 3, wn = w >> 2;                 // 4 warps along M, 2 along N
    int m_blk  = blockIdx.y * 128;
    int m_base = m_blk + wm * 32;                // batch rows (in-range)
    int n_blk  = blockIdx.x * 128;
    int n_base = n_blk + wn * 64;                // item cols (tail-predicated)
    int g = lane >> 2, tg = lane & 3;

    // ---- fill smem Wpb tile: rows n_blk..n_blk+127, uint4-coalesced ----
#pragma unroll
    for (int it = 0; it < 4; it++) {
        int i = it * 256 + tid;                  // 0..1023
        int row = i >> 3, off = i & 7;
        int gr = n_blk + row;
        uint4 v = make_uint4(0u, 0u, 0u, 0u);
        if (gr < NUM_ITEMS) v = *(const uint4*)&g_Wpb[(size_t)gr * 64 + off * 8];
        *(uint4*)&sWp[row * WP_STRIDE + off * 16] = v;
    }

    // ---- load + pack x tile [128 x 128] to smem bits, 4 loads in flight ----
    {
        int cb = n_blk + lane * 4;
        bool cok = (cb + 3) < NUM_ITEMS;         // tail chunk: some lanes OOB -> 0
#pragma unroll
        for (int it = 0; it < 4; it++) {
            float4 v[4];
#pragma unroll
            for (int j = 0; j < 4; j++) {
                int row = it * 32 + j * 8 + w;   // 0..127
                v[j] = make_float4(0.f, 0.f, 0.f, 0.f);
                if (cok) v[j] = __ldcs((const float4*)&x[(size_t)(m_blk + row) * NUM_ITEMS + cb]);
            }
#pragma unroll
            for (int j = 0; j < 4; j++) {
                int row = it * 32 + j * 8 + w;
                unsigned b0 = __ballot_sync(0xFFFFFFFFu, v[j].x != 0.f);
                unsigned b1 = __ballot_sync(0xFFFFFFFFu, v[j].y != 0.f);
                unsigned b2 = __ballot_sync(0xFFFFFFFFu, v[j].z != 0.f);
                unsigned b3 = __ballot_sync(0xFFFFFFFFu, v[j].w != 0.f);
                if (lane == 0) *(uint4*)&sX[row * 4] = make_uint4(b0, b1, b2, b3);
            }
        }
    }

    // ---- A fragments: z tile 32(M) x 64(K), register-resident ----
    unsigned a[2][4][4];
#pragma unroll
    for (int mf = 0; mf < 2; mf++) {
        int r0 = m_base + mf * 16 + g;
#pragma unroll
        for (int kf = 0; kf < 4; kf++) {
            int kb = kf * 16 + tg * 2;
            a[mf][kf][0] = *(const unsigned*)&g_zb[(r0)     * 64 + kb];
            a[mf][kf][1] = *(const unsigned*)&g_zb[(r0 + 8) * 64 + kb];
            a[mf][kf][2] = *(const unsigned*)&g_zb[(r0)     * 64 + kb + 8];
            a[mf][kf][3] = *(const unsigned*)&g_zb[(r0 + 8) * 64 + kb + 8];
        }
    }

    __syncthreads();

    // ---- x bitmask words: loop-invariant per result row (from smem) ----
    int v0   = (tg & 1) * 2;
    int tofs = wn * 16 + (tg >> 1);
    unsigned xw0[4], xw1[4];
#pragma unroll
    for (int li = 0; li < 4; li++) {
        int local = wm * 32 + (li >> 1) * 16 + (li & 1) * 8 + g;
        uint2 xv = *(const uint2*)&sX[local * 4 + v0];
        xw0[li] = xv.x; xw1[li] = xv.y;
    }

    float sexp[4] = {0, 0, 0, 0}, sdot[4] = {0, 0, 0, 0};

#pragma unroll
    for (int nf = 0; nf < 8; nf++) {
        // B fragments from smem (conflict-free LDS)
        int rloc = wn * 64 + nf * 8 + g;         // local smem row
        unsigned bf[4][2];
#pragma unroll
        for (int kf = 0; kf < 4; kf++) {
            bf[kf][0] = *(const unsigned*)&sWp[rloc * WP_STRIDE + kf * 32 + tg * 4];
            bf[kf][1] = *(const unsigned*)&sWp[rloc * WP_STRIDE + kf * 32 + tg * 4 + 16];
        }

        float d[2][4] = {{0, 0, 0, 0}, {0, 0, 0, 0}};
#pragma unroll
        for (int mf = 0; mf < 2; mf++)
#pragma unroll
            for (int kf = 0; kf < 4; kf++)
                mma16816(d[mf], a[mf][kf], bf[kf]);

        int c0 = n_base + nf * 8 + tg * 2;
        int t  = tofs + nf * 2;                  // bit position in xw words
        if (c0 < NUM_ITEMS) {
            float2 ebpv = *(const float2*)&g_ebp[c0];
#pragma unroll
            for (int mf = 0; mf < 2; mf++)
#pragma unroll
                for (int h = 0; h < 2; h++) {
                    int li = mf * 2 + h;
                    float d0 = d[mf][h * 2 + 0];
                    float d1 = d[mf][h * 2 + 1];
                    sexp[li] += __expf(d0) * ebpv.x + __expf(d1) * ebpv.y;
                    if ((xw0[li] >> t) & 1) sdot[li] += d0;
                    if ((xw1[li] >> t) & 1) sdot[li] += d1;
                }
        }
    }

    // reduce sexp/sdot across the 4 threads of each group, atomics per row
#pragma unroll
    for (int li = 0; li < 4; li++) {
        float se = sexp[li], sd = sdot[li];
#pragma unroll
        for (int o = 1; o < 4; o <<= 1) {
            se += __shfl_xor_sync(0xFFFFFFFFu, se, o);
            sd += __shfl_xor_sync(0xFFFFFFFFu, sd, o);
        }
        if (tg == 0) {
            int row = m_base + (li >> 1) * 16 + (li & 1) * 8 + g;
            atomicAdd(&g_sexp[row], se);
            atomicAdd(&g_sdot[row], sd);
        }
    }

    // ---- block-end: scnt via popcount, sdot bp-part via set-bit walk ----
    if (tid < 128) {
        int row = tid;
        int cnt = 0;
        float accbp = 0.f;
#pragma unroll
        for (int v = 0; v < 4; v++) {
            unsigned wv = sX[row * 4 + v];
            cnt += __popc(wv);
            while (wv) {
                int t2 = __ffs(wv) - 1; wv &= wv - 1;
                accbp += bp[n_blk + 4 * t2 + v];   // bits guaranteed in-range
            }
        }
        if (cnt)          atomicAdd(&g_scnt[m_blk + row], (float)cnt);
        if (accbp != 0.f) atomicAdd(&g_sdot[m_blk + row], accbp);
    }
}

// ---- 5: final reduction ----
__global__ void k_final(float* __restrict__ out) {
    __shared__ float sm[256];
    float acc = 0.f;
    for (int r = threadIdx.x; r < BATCH; r += 256)
        acc += g_scnt[r] * logf(g_sexp[r]) - g_sdot[r];
    sm[threadIdx.x] = acc;
    __syncthreads();
    for (int o = 128; o > 0; o >>= 1) {
        if (threadIdx.x < o) sm[threadIdx.x] += sm[threadIdx.x + o];
        __syncthreads();
    }
    if (threadIdx.x == 0) {
        out[0] = sm[0] / (float)BATCH;
        out[1] = -0.5f * g_kl / (float)BATCH;
    }
}

extern "C" void kernel_launch(void* const* d_in, const int* in_sizes, int n_in,
                              void* d_out, int out_size) {
    const float* graph_vals = (const float*)d_in[0];
    const float* Wq         = (const float*)d_in[1];
    const float* bq         = (const float*)d_in[2];
    const float* Wp         = (const float*)d_in[3];
    const float* bp         = (const float*)d_in[4];
    const float* x          = (const float*)d_in[5];
    const float* eps        = (const float*)d_in[6];
    const int*   graph_rows = (const int*)d_in[7];
    const int*   graph_cols = (const int*)d_in[8];
    const int*   user       = (const int*)d_in[9];
    float* out = (float*)d_out;

    k_prep<<<6920, 256>>>(Wq, Wp, bp, user);
    k_edges<<<(NNZ + 255) / 256, 256>>>(graph_vals, graph_rows, graph_cols, user);
    k_z<<<BATCH, 64>>>(bq, eps, user);
    {
        dim3 grid((NUM_ITEMS + 127) / 128, BATCH / 128);
        k_gemm<<<grid, 256>>>(bp, x);
    }
    k_final<<<1, 256>>>(out);
}

// round 14
// speedup vs baseline: 1.2089x; 1.0628x over previous
#include <cuda_runtime.h>
#include <cuda_bf16.h>
#include <cstdint>

#define NUM_USERS 50000
#define NUM_ITEMS 40000
#define EMB 64
#define NNZ 2000000
#define BATCH 1024

// ---- scratch (static __device__ globals; no allocation allowed) ----
__device__ float         g_WqT[NUM_ITEMS * 128];     // Wq transposed: [item][128]
__device__ __nv_bfloat16 g_Wpb[NUM_ITEMS * EMB];     // Wp in bf16:   [item][64]
__device__ float         g_hsel[BATCH * 128];        // selected-user h accumulators
__device__ int           g_map[NUM_USERS];           // user -> batch slot (validated by back-check)
__device__ __nv_bfloat16 g_zb[BATCH * EMB];          // z in bf16
__device__ float         g_sexp[BATCH];
__device__ float         g_sdot[BATCH];
__device__ float         g_scnt[BATCH];
__device__ float         g_kl;

__device__ __forceinline__ unsigned pack_bf162(float lo, float hi) {
    __nv_bfloat162 t = __floats2bfloat162_rn(lo, hi);
    return *(unsigned*)&t;
}

// ---- 1: fused prep: Wq transpose + Wp->bf16 + zero scratch + user map ----
__global__ void __launch_bounds__(256)
k_prep(const float* __restrict__ Wq, const float* __restrict__ Wp,
       const int* __restrict__ user) {
    __shared__ float tile[32][33];
    int bid = blockIdx.x, tid = threadIdx.x;
    if (bid < 5000) {
        int i0 = (bid % 1250) * 32, k0 = (bid / 1250) * 32;
        int tx = tid & 31, ty = tid >> 5;          // (32,8)
#pragma unroll
        for (int r = 0; r < 32; r += 8)
            tile[ty + r][tx] = Wq[(size_t)(k0 + ty + r) * NUM_ITEMS + i0 + tx];
        __syncthreads();
#pragma unroll
        for (int r = 0; r < 32; r += 8)
            g_WqT[(size_t)(i0 + ty + r) * 128 + k0 + tx] = tile[tx][ty + r];
    } else if (bid < 6250) {
        int i = (bid - 5000) * 256 + tid;          // < 320000 exactly
        const float4* in4 = (const float4*)Wp;
        float4 a = in4[2 * i], b = in4[2 * i + 1];
        uint4 o;
        o.x = pack_bf162(a.x, a.y);
        o.y = pack_bf162(a.z, a.w);
        o.z = pack_bf162(b.x, b.y);
        o.w = pack_bf162(b.z, b.w);
        ((uint4*)g_Wpb)[i] = o;
    } else if (bid < 6762) {
        int i = (bid - 6250) * 256 + tid;          // < 131072 exactly
        g_hsel[i] = 0.f;
    } else {
#pragma unroll
        for (int b = tid; b < BATCH; b += 256) {
            g_sexp[b] = 0.f; g_sdot[b] = 0.f; g_scnt[b] = 0.f;
            g_map[user[b]] = b;                    // racing store; any winner valid
        }
        if (tid == 0) g_kl = 0.f;
    }
}

// ---- 2: scatter kept edges; cols/vals loaded ONLY for kept (~2%) edges ----
__global__ void k_edges(const float* __restrict__ vals,
                        const int* __restrict__ rows,
                        const int* __restrict__ cols,
                        const int* __restrict__ user) {
    int idx  = blockIdx.x * blockDim.x + threadIdx.x;
    int lane = threadIdx.x & 31;
    int slot = -1, col = 0;
    float val = 0.f;
    if (idx < NNZ) {
        int r = rows[idx];
        int s = g_map[r];
        if ((unsigned)s < BATCH && __ldg(&user[s]) == r) {
            slot = s;
            col  = cols[idx];                      // sparse load, kept edges only
            val  = vals[idx];
        }
    }
    unsigned m = __ballot_sync(0xFFFFFFFFu, slot >= 0);
    while (m) {
        int j = __ffs(m) - 1; m &= m - 1;
        int   c = __shfl_sync(0xFFFFFFFFu, col, j);
        float v = __shfl_sync(0xFFFFFFFFu, val, j);
        int   s = __shfl_sync(0xFFFFFFFFu, slot, j);
        const float* wr = &g_WqT[(size_t)c * 128];
        float* hr = &g_hsel[s * 128];
#pragma unroll
        for (int k = lane; k < 128; k += 32)
            atomicAdd(&hr[k], v * wr[k]);
    }
}

// ---- 3: reparameterize + KL ----
__global__ void k_z(const float* __restrict__ bq,
                    const float* __restrict__ eps,
                    const int* __restrict__ user) {
    int b = blockIdx.x, k = threadIdx.x;   // 64 threads
    int u = user[b];
    int s = g_map[u];
    float mu = g_hsel[s * 128 + k]      + bq[k];
    float lv = g_hsel[s * 128 + 64 + k] + bq[64 + k];
    float z  = mu + eps[u * EMB + k] * __expf(0.5f * lv);
    g_zb[b * EMB + k] = __float2bfloat16(z);
    float t = 1.f + lv - mu * mu - __expf(lv);
#pragma unroll
    for (int o = 16; o > 0; o >>= 1) t += __shfl_down_sync(0xFFFFFFFFu, t, o);
    __shared__ float sm[2];
    if ((threadIdx.x & 31) == 0) sm[threadIdx.x >> 5] = t;
    __syncthreads();
    if (threadIdx.x == 0) atomicAdd(&g_kl, sm[0] + sm[1]);
}

// ---- 4: fused decoder GEMM (bf16 HMMA) + softmax-stats epilogue ----
// Wpb tile + bp slice + x bitmask ALL in smem: hot loop has ZERO global loads.
__device__ __forceinline__ void mma16816(float* d, const unsigned* a, const unsigned* b) {
    asm volatile(
        "mma.sync.aligned.m16n8k16.row.col.f32.bf16.bf16.f32 "
        "{%0,%1,%2,%3}, {%4,%5,%6,%7}, {%8,%9}, {%0,%1,%2,%3};\n"
        : "+f"(d[0]), "+f"(d[1]), "+f"(d[2]), "+f"(d[3])
        : "r"(a[0]), "r"(a[1]), "r"(a[2]), "r"(a[3]), "r"(b[0]), "r"(b[1]));
}

#define WP_STRIDE 144   // bytes per smem row: 128 data + 16 pad (bank-conflict-free)

__global__ void __launch_bounds__(256, 3)
k_gemm(const float* __restrict__ bp, const float* __restrict__ x) {
    __shared__ __align__(16) unsigned char sWp[128 * WP_STRIDE];   // 18 KB
    __shared__ __align__(16) unsigned sX[128 * 4];                 // 2 KB bitmask
    __shared__ float sBp[128];                                     // 512 B

    int tid = threadIdx.x;
    int w = tid >> 5, lane = tid & 31;
    int wm = w & 3, wn = w >> 2;                 // 4 warps along M, 2 along N
    int m_blk  = blockIdx.y * 128;
    int m_base = m_blk + wm * 32;                // batch rows (in-range)
    int n_blk  = blockIdx.x * 128;
    int n_base = n_blk + wn * 64;                // item cols (tail-predicated)
    int g = lane >> 2, tg = lane & 3;

    // ---- stage bp slice (512B) ----
    if (tid < 128) {
        int gc = n_blk + tid;
        sBp[tid] = (gc < NUM_ITEMS) ? bp[gc] : 0.f;
    }

    // ---- fill smem Wpb tile: rows n_blk..n_blk+127, uint4-coalesced ----
#pragma unroll
    for (int it = 0; it < 4; it++) {
        int i = it * 256 + tid;                  // 0..1023
        int row = i >> 3, off = i & 7;
        int gr = n_blk + row;
        uint4 v = make_uint4(0u, 0u, 0u, 0u);
        if (gr < NUM_ITEMS) v = *(const uint4*)&g_Wpb[(size_t)gr * 64 + off * 8];
        *(uint4*)&sWp[row * WP_STRIDE + off * 16] = v;
    }

    // ---- load + pack x tile [128 x 128] to smem bits, 4 loads in flight ----
    {
        int cb = n_blk + lane * 4;
        bool cok = (cb + 3) < NUM_ITEMS;
#pragma unroll
        for (int it = 0; it < 4; it++) {
            float4 v[4];
#pragma unroll
            for (int j = 0; j < 4; j++) {
                int row = it * 32 + j * 8 + w;   // 0..127
                v[j] = make_float4(0.f, 0.f, 0.f, 0.f);
                if (cok) v[j] = __ldcs((const float4*)&x[(size_t)(m_blk + row) * NUM_ITEMS + cb]);
            }
#pragma unroll
            for (int j = 0; j < 4; j++) {
                int row = it * 32 + j * 8 + w;
                unsigned b0 = __ballot_sync(0xFFFFFFFFu, v[j].x != 0.f);
                unsigned b1 = __ballot_sync(0xFFFFFFFFu, v[j].y != 0.f);
                unsigned b2 = __ballot_sync(0xFFFFFFFFu, v[j].z != 0.f);
                unsigned b3 = __ballot_sync(0xFFFFFFFFu, v[j].w != 0.f);
                if (lane == 0) *(uint4*)&sX[row * 4] = make_uint4(b0, b1, b2, b3);
            }
        }
    }

    // ---- A fragments: z tile 32(M) x 64(K), register-resident ----
    unsigned a[2][4][4];
#pragma unroll
    for (int mf = 0; mf < 2; mf++) {
        int r0 = m_base + mf * 16 + g;
#pragma unroll
        for (int kf = 0; kf < 4; kf++) {
            int kb = kf * 16 + tg * 2;
            a[mf][kf][0] = *(const unsigned*)&g_zb[(r0)     * 64 + kb];
            a[mf][kf][1] = *(const unsigned*)&g_zb[(r0 + 8) * 64 + kb];
            a[mf][kf][2] = *(const unsigned*)&g_zb[(r0)     * 64 + kb + 8];
            a[mf][kf][3] = *(const unsigned*)&g_zb[(r0 + 8) * 64 + kb + 8];
        }
    }

    __syncthreads();

    // ---- x bitmask words: loop-invariant per result row (from smem) ----
    int v0   = (tg & 1) * 2;
    int tofs = wn * 16 + (tg >> 1);
    unsigned xw0[4], xw1[4];
#pragma unroll
    for (int li = 0; li < 4; li++) {
        int local = wm * 32 + (li >> 1) * 16 + (li & 1) * 8 + g;
        uint2 xv = *(const uint2*)&sX[local * 4 + v0];
        xw0[li] = xv.x; xw1[li] = xv.y;
    }

    float sexp[4] = {0, 0, 0, 0}, sdot[4] = {0, 0, 0, 0}, scnt[4] = {0, 0, 0, 0};

#pragma unroll
    for (int nf = 0; nf < 8; nf++) {
        // B fragments from smem (conflict-free LDS)
        int rloc = wn * 64 + nf * 8 + g;         // local smem row
        unsigned bf[4][2];
#pragma unroll
        for (int kf = 0; kf < 4; kf++) {
            bf[kf][0] = *(const unsigned*)&sWp[rloc * WP_STRIDE + kf * 32 + tg * 4];
            bf[kf][1] = *(const unsigned*)&sWp[rloc * WP_STRIDE + kf * 32 + tg * 4 + 16];
        }

        float d[2][4] = {{0, 0, 0, 0}, {0, 0, 0, 0}};
#pragma unroll
        for (int mf = 0; mf < 2; mf++)
#pragma unroll
            for (int kf = 0; kf < 4; kf++)
                mma16816(d[mf], a[mf][kf], bf[kf]);

        int c0 = n_base + nf * 8 + tg * 2;
        int t  = tofs + nf * 2;                  // bit position in xw words
        if (c0 < NUM_ITEMS) {
            float2 bpv = *(const float2*)&sBp[wn * 64 + nf * 8 + tg * 2];
#pragma unroll
            for (int mf = 0; mf < 2; mf++)
#pragma unroll
                for (int h = 0; h < 2; h++) {
                    int li = mf * 2 + h;
                    float v0f = d[mf][h * 2 + 0] + bpv.x;
                    float v1f = d[mf][h * 2 + 1] + bpv.y;
                    sexp[li] += __expf(v0f) + __expf(v1f);
                    if ((xw0[li] >> t) & 1) { sdot[li] += v0f; scnt[li] += 1.f; }
                    if ((xw1[li] >> t) & 1) { sdot[li] += v1f; scnt[li] += 1.f; }
                }
        }
    }

    // reduce across the 4 threads of each group (tg), then atomics per row
#pragma unroll
    for (int li = 0; li < 4; li++) {
        float se = sexp[li], sd = sdot[li], sc = scnt[li];
#pragma unroll
        for (int o = 1; o < 4; o <<= 1) {
            se += __shfl_xor_sync(0xFFFFFFFFu, se, o);
            sd += __shfl_xor_sync(0xFFFFFFFFu, sd, o);
            sc += __shfl_xor_sync(0xFFFFFFFFu, sc, o);
        }
        if (tg == 0) {
            int row = m_base + (li >> 1) * 16 + (li & 1) * 8 + g;
            atomicAdd(&g_sexp[row], se);
            atomicAdd(&g_sdot[row], sd);
            atomicAdd(&g_scnt[row], sc);
        }
    }
}

// ---- 5: final reduction ----
__global__ void k_final(float* __restrict__ out) {
    __shared__ float sm[256];
    float acc = 0.f;
    for (int r = threadIdx.x; r < BATCH; r += 256)
        acc += g_scnt[r] * logf(g_sexp[r]) - g_sdot[r];
    sm[threadIdx.x] = acc;
    __syncthreads();
    for (int o = 128; o > 0; o >>= 1) {
        if (threadIdx.x < o) sm[threadIdx.x] += sm[threadIdx.x + o];
        __syncthreads();
    }
    if (threadIdx.x == 0) {
        out[0] = sm[0] / (float)BATCH;
        out[1] = -0.5f * g_kl / (float)BATCH;
    }
}

extern "C" void kernel_launch(void* const* d_in, const int* in_sizes, int n_in,
                              void* d_out, int out_size) {
    const float* graph_vals = (const float*)d_in[0];
    const float* Wq         = (const float*)d_in[1];
    const float* bq         = (const float*)d_in[2];
    const float* Wp         = (const float*)d_in[3];
    const float* bp         = (const float*)d_in[4];
    const float* x          = (const float*)d_in[5];
    const float* eps        = (const float*)d_in[6];
    const int*   graph_rows = (const int*)d_in[7];
    const int*   graph_cols = (const int*)d_in[8];
    const int*   user       = (const int*)d_in[9];
    float* out = (float*)d_out;

    k_prep<<<6763, 256>>>(Wq, Wp, user);
    k_edges<<<(NNZ + 255) / 256, 256>>>(graph_vals, graph_rows, graph_cols, user);
    k_z<<<BATCH, 64>>>(bq, eps, user);
    {
        dim3 grid((NUM_ITEMS + 127) / 128, BATCH / 128);
        k_gemm<<<grid, 256>>>(bp, x);
    }
    k_final<<<1, 256>>>(out);
}

// round 15
// speedup vs baseline: 1.2835x; 1.0617x over previous
#include <cuda_runtime.h>
#include <cuda_bf16.h>
#include <cstdint>

#define NUM_USERS 50000
#define NUM_ITEMS 40000
#define EMB 64
#define NNZ 2000000
#define BATCH 1024
#define LOG2E 1.4426950408889634f
#define LN2   0.6931471805599453f

// ---- scratch (static __device__ globals; no allocation allowed) ----
__device__ float         g_WqT[NUM_ITEMS * 128];     // Wq transposed: [item][128]
__device__ __nv_bfloat16 g_Wpb[NUM_ITEMS * EMB];     // Wp in bf16:   [item][64]
__device__ float         g_hsel[BATCH * 128];        // selected-user h accumulators
__device__ int           g_map[NUM_USERS];           // user -> batch slot (validated by back-check)
__device__ __nv_bfloat16 g_zb[BATCH * EMB];          // z * log2(e) in bf16
__device__ float         g_sexp[BATCH];
__device__ float         g_sdot[BATCH];              // in log2e scale; *LN2 at the end
__device__ float         g_scnt[BATCH];
__device__ float         g_kl;

__device__ __forceinline__ unsigned pack_bf162(float lo, float hi) {
    __nv_bfloat162 t = __floats2bfloat162_rn(lo, hi);
    return *(unsigned*)&t;
}
__device__ __forceinline__ float ex2f(float v) {
    float r; asm("ex2.approx.ftz.f32 %0, %1;" : "=f"(r) : "f"(v)); return r;
}

// ---- 1: fused prep: Wq transpose + Wp->bf16 + zero scratch + user map ----
__global__ void __launch_bounds__(256)
k_prep(const float* __restrict__ Wq, const float* __restrict__ Wp,
       const int* __restrict__ user) {
    __shared__ float tile[32][33];
    int bid = blockIdx.x, tid = threadIdx.x;
    if (bid < 5000) {
        int i0 = (bid % 1250) * 32, k0 = (bid / 1250) * 32;
        int tx = tid & 31, ty = tid >> 5;          // (32,8)
#pragma unroll
        for (int r = 0; r < 32; r += 8)
            tile[ty + r][tx] = Wq[(size_t)(k0 + ty + r) * NUM_ITEMS + i0 + tx];
        __syncthreads();
#pragma unroll
        for (int r = 0; r < 32; r += 8)
            g_WqT[(size_t)(i0 + ty + r) * 128 + k0 + tx] = tile[tx][ty + r];
    } else if (bid < 6250) {
        int i = (bid - 5000) * 256 + tid;          // < 320000 exactly
        const float4* in4 = (const float4*)Wp;
        float4 a = in4[2 * i], b = in4[2 * i + 1];
        uint4 o;
        o.x = pack_bf162(a.x, a.y);
        o.y = pack_bf162(a.z, a.w);
        o.z = pack_bf162(b.x, b.y);
        o.w = pack_bf162(b.z, b.w);
        ((uint4*)g_Wpb)[i] = o;
    } else if (bid < 6762) {
        int i = (bid - 6250) * 256 + tid;          // < 131072 exactly
        g_hsel[i] = 0.f;
    } else {
#pragma unroll
        for (int b = tid; b < BATCH; b += 256) {
            g_sexp[b] = 0.f; g_sdot[b] = 0.f; g_scnt[b] = 0.f;
            g_map[user[b]] = b;                    // racing store; any winner valid
        }
        if (tid == 0) g_kl = 0.f;
    }
}

// ---- 2: scatter kept edges; cols/vals loaded ONLY for kept (~2%) edges ----
__global__ void k_edges(const float* __restrict__ vals,
                        const int* __restrict__ rows,
                        const int* __restrict__ cols,
                        const int* __restrict__ user) {
    int idx  = blockIdx.x * blockDim.x + threadIdx.x;
    int lane = threadIdx.x & 31;
    int slot = -1, col = 0;
    float val = 0.f;
    if (idx < NNZ) {
        int r = rows[idx];
        int s = g_map[r];
        if ((unsigned)s < BATCH && __ldg(&user[s]) == r) {
            slot = s;
            col  = cols[idx];                      // sparse load, kept edges only
            val  = vals[idx];
        }
    }
    unsigned m = __ballot_sync(0xFFFFFFFFu, slot >= 0);
    while (m) {
        int j = __ffs(m) - 1; m &= m - 1;
        int   c = __shfl_sync(0xFFFFFFFFu, col, j);
        float v = __shfl_sync(0xFFFFFFFFu, val, j);
        int   s = __shfl_sync(0xFFFFFFFFu, slot, j);
        const float* wr = &g_WqT[(size_t)c * 128];
        float* hr = &g_hsel[s * 128];
#pragma unroll
        for (int k = lane; k < 128; k += 32)
            atomicAdd(&hr[k], v * wr[k]);
    }
}

// ---- 3: reparameterize + KL; z stored pre-scaled by log2(e) ----
__global__ void k_z(const float* __restrict__ bq,
                    const float* __restrict__ eps,
                    const int* __restrict__ user) {
    int b = blockIdx.x, k = threadIdx.x;   // 64 threads
    int u = user[b];
    int s = g_map[u];
    float mu = g_hsel[s * 128 + k]      + bq[k];
    float lv = g_hsel[s * 128 + 64 + k] + bq[64 + k];
    float z  = mu + eps[u * EMB + k] * __expf(0.5f * lv);
    g_zb[b * EMB + k] = __float2bfloat16(z * LOG2E);
    float t = 1.f + lv - mu * mu - __expf(lv);
#pragma unroll
    for (int o = 16; o > 0; o >>= 1) t += __shfl_down_sync(0xFFFFFFFFu, t, o);
    __shared__ float sm[2];
    if ((threadIdx.x & 31) == 0) sm[threadIdx.x >> 5] = t;
    __syncthreads();
    if (threadIdx.x == 0) atomicAdd(&g_kl, sm[0] + sm[1]);
}

// ---- 4: fused decoder GEMM (bf16 HMMA) + thinned epilogue ----
// d accumulators seeded with bp*log2e (free); epilogue = EX2 + FADD + bit-test
// sdot only; scnt via popcount of sX at block end.
__device__ __forceinline__ void mma16816(float* d, const unsigned* a, const unsigned* b) {
    asm volatile(
        "mma.sync.aligned.m16n8k16.row.col.f32.bf16.bf16.f32 "
        "{%0,%1,%2,%3}, {%4,%5,%6,%7}, {%8,%9}, {%0,%1,%2,%3};\n"
        : "+f"(d[0]), "+f"(d[1]), "+f"(d[2]), "+f"(d[3])
        : "r"(a[0]), "r"(a[1]), "r"(a[2]), "r"(a[3]), "r"(b[0]), "r"(b[1]));
}

#define WP_STRIDE 144   // bytes per smem row: 128 data + 16 pad (bank-conflict-free)

__global__ void __launch_bounds__(256, 3)
k_gemm(const float* __restrict__ bp, const float* __restrict__ x) {
    __shared__ __align__(16) unsigned char sWp[128 * WP_STRIDE];   // 18 KB
    __shared__ __align__(16) unsigned sX[128 * 4];                 // 2 KB bitmask
    __shared__ float sBp[128];                                     // bp * log2e

    int tid = threadIdx.x;
    int w = tid >> 5, lane = tid & 31;
    int wm = w & 3, wn = w >> 2;                 // 4 warps along M, 2 along N
    int m_blk  = blockIdx.y * 128;
    int m_base = m_blk + wm * 32;                // batch rows (in-range)
    int n_blk  = blockIdx.x * 128;
    int n_base = n_blk + wn * 64;                // item cols (tail-predicated)
    int g = lane >> 2, tg = lane & 3;

    // ---- stage bp*log2e slice ----
    if (tid < 128) {
        int gc = n_blk + tid;
        sBp[tid] = (gc < NUM_ITEMS) ? bp[gc] * LOG2E : 0.f;
    }

    // ---- fill smem Wpb tile: rows n_blk..n_blk+127, uint4-coalesced ----
#pragma unroll
    for (int it = 0; it < 4; it++) {
        int i = it * 256 + tid;                  // 0..1023
        int row = i >> 3, off = i & 7;
        int gr = n_blk + row;
        uint4 v = make_uint4(0u, 0u, 0u, 0u);
        if (gr < NUM_ITEMS) v = *(const uint4*)&g_Wpb[(size_t)gr * 64 + off * 8];
        *(uint4*)&sWp[row * WP_STRIDE + off * 16] = v;
    }

    // ---- load + pack x tile [128 x 128] to smem bits, 4 loads in flight ----
    {
        int cb = n_blk + lane * 4;
        bool cok = (cb + 3) < NUM_ITEMS;
#pragma unroll
        for (int it = 0; it < 4; it++) {
            float4 v[4];
#pragma unroll
            for (int j = 0; j < 4; j++) {
                int row = it * 32 + j * 8 + w;   // 0..127
                v[j] = make_float4(0.f, 0.f, 0.f, 0.f);
                if (cok) v[j] = __ldcs((const float4*)&x[(size_t)(m_blk + row) * NUM_ITEMS + cb]);
            }
#pragma unroll
            for (int j = 0; j < 4; j++) {
                int row = it * 32 + j * 8 + w;
                unsigned b0 = __ballot_sync(0xFFFFFFFFu, v[j].x != 0.f);
                unsigned b1 = __ballot_sync(0xFFFFFFFFu, v[j].y != 0.f);
                unsigned b2 = __ballot_sync(0xFFFFFFFFu, v[j].z != 0.f);
                unsigned b3 = __ballot_sync(0xFFFFFFFFu, v[j].w != 0.f);
                if (lane == 0) *(uint4*)&sX[row * 4] = make_uint4(b0, b1, b2, b3);
            }
        }
    }

    // ---- A fragments: z tile 32(M) x 64(K), register-resident ----
    unsigned a[2][4][4];
#pragma unroll
    for (int mf = 0; mf < 2; mf++) {
        int r0 = m_base + mf * 16 + g;
#pragma unroll
        for (int kf = 0; kf < 4; kf++) {
            int kb = kf * 16 + tg * 2;
            a[mf][kf][0] = *(const unsigned*)&g_zb[(r0)     * 64 + kb];
            a[mf][kf][1] = *(const unsigned*)&g_zb[(r0 + 8) * 64 + kb];
            a[mf][kf][2] = *(const unsigned*)&g_zb[(r0)     * 64 + kb + 8];
            a[mf][kf][3] = *(const unsigned*)&g_zb[(r0 + 8) * 64 + kb + 8];
        }
    }

    __syncthreads();

    // ---- x bitmask words: loop-invariant per result row (from smem) ----
    int v0   = (tg & 1) * 2;
    int tofs = wn * 16 + (tg >> 1);
    unsigned xw0[4], xw1[4];
#pragma unroll
    for (int li = 0; li < 4; li++) {
        int local = wm * 32 + (li >> 1) * 16 + (li & 1) * 8 + g;
        uint2 xv = *(const uint2*)&sX[local * 4 + v0];
        xw0[li] = xv.x; xw1[li] = xv.y;
    }

    float sexp[4] = {0, 0, 0, 0}, sdot[4] = {0, 0, 0, 0};

#pragma unroll
    for (int nf = 0; nf < 8; nf++) {
        // B fragments from smem (conflict-free LDS)
        int rloc = wn * 64 + nf * 8 + g;         // local smem row
        unsigned bf[4][2];
#pragma unroll
        for (int kf = 0; kf < 4; kf++) {
            bf[kf][0] = *(const unsigned*)&sWp[rloc * WP_STRIDE + kf * 32 + tg * 4];
            bf[kf][1] = *(const unsigned*)&sWp[rloc * WP_STRIDE + kf * 32 + tg * 4 + 16];
        }

        // d seeded with bp*log2e (replaces zero-init MOVs; bp-add now free)
        float2 bpv = *(const float2*)&sBp[wn * 64 + nf * 8 + tg * 2];
        float d[2][4] = {{bpv.x, bpv.y, bpv.x, bpv.y},
                         {bpv.x, bpv.y, bpv.x, bpv.y}};
#pragma unroll
        for (int mf = 0; mf < 2; mf++)
#pragma unroll
            for (int kf = 0; kf < 4; kf++)
                mma16816(d[mf], a[mf][kf], bf[kf]);

        int c0 = n_base + nf * 8 + tg * 2;
        int t  = tofs + nf * 2;                  // bit position in xw words
        if (c0 < NUM_ITEMS) {
#pragma unroll
            for (int mf = 0; mf < 2; mf++)
#pragma unroll
                for (int h = 0; h < 2; h++) {
                    int li = mf * 2 + h;
                    float d0 = d[mf][h * 2 + 0];
                    float d1 = d[mf][h * 2 + 1];
                    sexp[li] += ex2f(d0) + ex2f(d1);
                    if ((xw0[li] >> t) & 1) sdot[li] += d0;
                    if ((xw1[li] >> t) & 1) sdot[li] += d1;
                }
        }
    }

    // reduce sexp/sdot across the 4 threads of each group, atomics per row
#pragma unroll
    for (int li = 0; li < 4; li++) {
        float se = sexp[li], sd = sdot[li];
#pragma unroll
        for (int o = 1; o < 4; o <<= 1) {
            se += __shfl_xor_sync(0xFFFFFFFFu, se, o);
            sd += __shfl_xor_sync(0xFFFFFFFFu, sd, o);
        }
        if (tg == 0) {
            int row = m_base + (li >> 1) * 16 + (li & 1) * 8 + g;
            atomicAdd(&g_sexp[row], se);
            atomicAdd(&g_sdot[row], sd);
        }
    }

    // ---- block-end: scnt via popcount of the x bitmask ----
    if (tid < 128) {
        uint4 wv = *(const uint4*)&sX[tid * 4];
        int cnt = __popc(wv.x) + __popc(wv.y) + __popc(wv.z) + __popc(wv.w);
        if (cnt) atomicAdd(&g_scnt[m_blk + tid], (float)cnt);
    }
}

// ---- 5: final reduction (sdot is in log2e scale -> *LN2) ----
__global__ void k_final(float* __restrict__ out) {
    __shared__ float sm[256];
    float acc = 0.f;
    for (int r = threadIdx.x; r < BATCH; r += 256)
        acc += g_scnt[r] * logf(g_sexp[r]) - g_sdot[r] * LN2;
    sm[threadIdx.x] = acc;
    __syncthreads();
    for (int o = 128; o > 0; o >>= 1) {
        if (threadIdx.x < o) sm[threadIdx.x] += sm[threadIdx.x + o];
        __syncthreads();
    }
    if (threadIdx.x == 0) {
        out[0] = sm[0] / (float)BATCH;
        out[1] = -0.5f * g_kl / (float)BATCH;
    }
}

extern "C" void kernel_launch(void* const* d_in, const int* in_sizes, int n_in,
                              void* d_out, int out_size) {
    const float* graph_vals = (const float*)d_in[0];
    const float* Wq         = (const float*)d_in[1];
    const float* bq         = (const float*)d_in[2];
    const float* Wp         = (const float*)d_in[3];
    const float* bp         = (const float*)d_in[4];
    const float* x          = (const float*)d_in[5];
    const float* eps        = (const float*)d_in[6];
    const int*   graph_rows = (const int*)d_in[7];
    const int*   graph_cols = (const int*)d_in[8];
    const int*   user       = (const int*)d_in[9];
    float* out = (float*)d_out;

    k_prep<<<6763, 256>>>(Wq, Wp, user);
    k_edges<<<(NNZ + 255) / 256, 256>>>(graph_vals, graph_rows, graph_cols, user);
    k_z<<<BATCH, 64>>>(bq, eps, user);
    {
        dim3 grid((NUM_ITEMS + 127) / 128, BATCH / 128);
        k_gemm<<<grid, 256>>>(bp, x);
    }
    k_final<<<1, 256>>>(out);
}

// round 16
// speedup vs baseline: 1.4123x; 1.1003x over previous
#include <cuda_runtime.h>
#include <cuda_bf16.h>
#include <cstdint>

#define NUM_USERS 50000
#define NUM_ITEMS 40000
#define EMB 64
#define NNZ 2000000
#define BATCH 1024
#define LOG2E 1.4426950408889634f
#define LN2   0.6931471805599453f

// ---- scratch (static __device__ globals; no allocation allowed) ----
__device__ float         g_WqT[NUM_ITEMS * 128];     // Wq transposed: [item][128]
__device__ __nv_bfloat16 g_Wpb[NUM_ITEMS * EMB];     // Wp in bf16:   [item][64]
__device__ float         g_hsel[BATCH * 128];        // selected-user h accumulators
__device__ int           g_map[NUM_USERS];           // user -> batch slot (validated by back-check)
__device__ __nv_bfloat16 g_zb[BATCH * EMB];          // z * log2(e) in bf16
__device__ float         g_sexp[BATCH];
__device__ float         g_sdot[BATCH];              // in log2e scale; *LN2 at the end
__device__ float         g_scnt[BATCH];
__device__ float         g_kl;

__device__ __forceinline__ unsigned pack_bf162(float lo, float hi) {
    __nv_bfloat162 t = __floats2bfloat162_rn(lo, hi);
    return *(unsigned*)&t;
}
__device__ __forceinline__ float ex2f(float v) {
    float r; asm("ex2.approx.ftz.f32 %0, %1;" : "=f"(r) : "f"(v)); return r;
}

// ---- 1: fused prep: Wq transpose + Wp->bf16 + zero scratch + user map ----
__global__ void __launch_bounds__(256)
k_prep(const float* __restrict__ Wq, const float* __restrict__ Wp,
       const int* __restrict__ user) {
    __shared__ float tile[32][33];
    int bid = blockIdx.x, tid = threadIdx.x;
    if (bid < 5000) {
        int i0 = (bid % 1250) * 32, k0 = (bid / 1250) * 32;
        int tx = tid & 31, ty = tid >> 5;          // (32,8)
#pragma unroll
        for (int r = 0; r < 32; r += 8)
            tile[ty + r][tx] = Wq[(size_t)(k0 + ty + r) * NUM_ITEMS + i0 + tx];
        __syncthreads();
#pragma unroll
        for (int r = 0; r < 32; r += 8)
            g_WqT[(size_t)(i0 + ty + r) * 128 + k0 + tx] = tile[tx][ty + r];
    } else if (bid < 6250) {
        int i = (bid - 5000) * 256 + tid;          // < 320000 exactly
        const float4* in4 = (const float4*)Wp;
        float4 a = in4[2 * i], b = in4[2 * i + 1];
        uint4 o;
        o.x = pack_bf162(a.x, a.y);
        o.y = pack_bf162(a.z, a.w);
        o.z = pack_bf162(b.x, b.y);
        o.w = pack_bf162(b.z, b.w);
        ((uint4*)g_Wpb)[i] = o;
    } else if (bid < 6762) {
        int i = (bid - 6250) * 256 + tid;          // < 131072 exactly
        g_hsel[i] = 0.f;
    } else {
#pragma unroll
        for (int b = tid; b < BATCH; b += 256) {
            g_sexp[b] = 0.f; g_sdot[b] = 0.f; g_scnt[b] = 0.f;
            g_map[user[b]] = b;                    // racing store; any winner valid
        }
        if (tid == 0) g_kl = 0.f;
    }
}

// ---- 2: scatter kept edges; cols/vals loaded ONLY for kept (~2%) edges ----
__global__ void k_edges(const float* __restrict__ vals,
                        const int* __restrict__ rows,
                        const int* __restrict__ cols,
                        const int* __restrict__ user) {
    int idx  = blockIdx.x * blockDim.x + threadIdx.x;
    int lane = threadIdx.x & 31;
    int slot = -1, col = 0;
    float val = 0.f;
    if (idx < NNZ) {
        int r = rows[idx];
        int s = g_map[r];
        if ((unsigned)s < BATCH && __ldg(&user[s]) == r) {
            slot = s;
            col  = cols[idx];                      // sparse load, kept edges only
            val  = vals[idx];
        }
    }
    unsigned m = __ballot_sync(0xFFFFFFFFu, slot >= 0);
    while (m) {
        int j = __ffs(m) - 1; m &= m - 1;
        int   c = __shfl_sync(0xFFFFFFFFu, col, j);
        float v = __shfl_sync(0xFFFFFFFFu, val, j);
        int   s = __shfl_sync(0xFFFFFFFFu, slot, j);
        const float* wr = &g_WqT[(size_t)c * 128];
        float* hr = &g_hsel[s * 128];
#pragma unroll
        for (int k = lane; k < 128; k += 32)
            atomicAdd(&hr[k], v * wr[k]);
    }
}

// ---- 3: reparameterize + KL; z stored pre-scaled by log2(e) ----
__global__ void k_z(const float* __restrict__ bq,
                    const float* __restrict__ eps,
                    const int* __restrict__ user) {
    int b = blockIdx.x, k = threadIdx.x;   // 64 threads
    int u = user[b];
    int s = g_map[u];
    float mu = g_hsel[s * 128 + k]      + bq[k];
    float lv = g_hsel[s * 128 + 64 + k] + bq[64 + k];
    float z  = mu + eps[u * EMB + k] * __expf(0.5f * lv);
    g_zb[b * EMB + k] = __float2bfloat16(z * LOG2E);
    float t = 1.f + lv - mu * mu - __expf(lv);
#pragma unroll
    for (int o = 16; o > 0; o >>= 1) t += __shfl_down_sync(0xFFFFFFFFu, t, o);
    __shared__ float sm[2];
    if ((threadIdx.x & 31) == 0) sm[threadIdx.x >> 5] = t;
    __syncthreads();
    if (threadIdx.x == 0) atomicAdd(&g_kl, sm[0] + sm[1]);
}

// ---- 4: fused decoder GEMM (bf16 HMMA) + thinned epilogue ----
// z tile AND Wp tile staged via coalesced uint4 -> smem; A/B fragments via
// conflict-free LDS (kills the 1024-wavefront scattered-LDG A path).
__device__ __forceinline__ void mma16816(float* d, const unsigned* a, const unsigned* b) {
    asm volatile(
        "mma.sync.aligned.m16n8k16.row.col.f32.bf16.bf16.f32 "
        "{%0,%1,%2,%3}, {%4,%5,%6,%7}, {%8,%9}, {%0,%1,%2,%3};\n"
        : "+f"(d[0]), "+f"(d[1]), "+f"(d[2]), "+f"(d[3])
        : "r"(a[0]), "r"(a[1]), "r"(a[2]), "r"(a[3]), "r"(b[0]), "r"(b[1]));
}

#define WP_STRIDE 144   // bytes per smem row: 128 data + 16 pad (bank-conflict-free)

__global__ void __launch_bounds__(256, 3)
k_gemm(const float* __restrict__ bp, const float* __restrict__ x) {
    __shared__ __align__(16) unsigned char sWp[128 * WP_STRIDE];   // 18 KB
    __shared__ __align__(16) unsigned char sZ[128 * WP_STRIDE];    // 18 KB
    __shared__ __align__(16) unsigned sX[128 * 4];                 // 2 KB bitmask
    __shared__ float sBp[128];                                     // bp * log2e

    int tid = threadIdx.x;
    int w = tid >> 5, lane = tid & 31;
    int wm = w & 3, wn = w >> 2;                 // 4 warps along M, 2 along N
    int m_blk  = blockIdx.y * 128;
    int m_base = m_blk + wm * 32;                // batch rows (in-range)
    int n_blk  = blockIdx.x * 128;
    int n_base = n_blk + wn * 64;                // item cols (tail-predicated)
    int g = lane >> 2, tg = lane & 3;

    // ---- stage bp*log2e slice ----
    if (tid < 128) {
        int gc = n_blk + tid;
        sBp[tid] = (gc < NUM_ITEMS) ? bp[gc] * LOG2E : 0.f;
    }

    // ---- fill smem Wpb tile (rows n_blk..+127) and z tile (rows m_blk..+127) ----
#pragma unroll
    for (int it = 0; it < 4; it++) {
        int i = it * 256 + tid;                  // 0..1023
        int row = i >> 3, off = i & 7;
        int gr = n_blk + row;
        uint4 v = make_uint4(0u, 0u, 0u, 0u);
        if (gr < NUM_ITEMS) v = *(const uint4*)&g_Wpb[(size_t)gr * 64 + off * 8];
        *(uint4*)&sWp[row * WP_STRIDE + off * 16] = v;
        // z rows always in range (BATCH covered exactly by grid.y)
        uint4 vz = *(const uint4*)&g_zb[(size_t)(m_blk + row) * 64 + off * 8];
        *(uint4*)&sZ[row * WP_STRIDE + off * 16] = vz;
    }

    // ---- load + pack x tile [128 x 128] to smem bits, 4 loads in flight ----
    {
        int cb = n_blk + lane * 4;
        bool cok = (cb + 3) < NUM_ITEMS;
#pragma unroll
        for (int it = 0; it < 4; it++) {
            float4 v[4];
#pragma unroll
            for (int j = 0; j < 4; j++) {
                int row = it * 32 + j * 8 + w;   // 0..127
                v[j] = make_float4(0.f, 0.f, 0.f, 0.f);
                if (cok) v[j] = __ldcs((const float4*)&x[(size_t)(m_blk + row) * NUM_ITEMS + cb]);
            }
#pragma unroll
            for (int j = 0; j < 4; j++) {
                int row = it * 32 + j * 8 + w;
                unsigned b0 = __ballot_sync(0xFFFFFFFFu, v[j].x != 0.f);
                unsigned b1 = __ballot_sync(0xFFFFFFFFu, v[j].y != 0.f);
                unsigned b2 = __ballot_sync(0xFFFFFFFFu, v[j].z != 0.f);
                unsigned b3 = __ballot_sync(0xFFFFFFFFu, v[j].w != 0.f);
                if (lane == 0) *(uint4*)&sX[row * 4] = make_uint4(b0, b1, b2, b3);
            }
        }
    }

    __syncthreads();

    // ---- A fragments: z tile 32(M) x 64(K) via conflict-free LDS ----
    unsigned a[2][4][4];
#pragma unroll
    for (int mf = 0; mf < 2; mf++) {
        int r0 = wm * 32 + mf * 16 + g;          // local smem row
#pragma unroll
        for (int kf = 0; kf < 4; kf++) {
            int kb2 = kf * 32 + tg * 4;          // byte offset of kb*2
            a[mf][kf][0] = *(const unsigned*)&sZ[(r0)     * WP_STRIDE + kb2];
            a[mf][kf][1] = *(const unsigned*)&sZ[(r0 + 8) * WP_STRIDE + kb2];
            a[mf][kf][2] = *(const unsigned*)&sZ[(r0)     * WP_STRIDE + kb2 + 16];
            a[mf][kf][3] = *(const unsigned*)&sZ[(r0 + 8) * WP_STRIDE + kb2 + 16];
        }
    }

    // ---- x bitmask words: loop-invariant per result row (from smem) ----
    int v0   = (tg & 1) * 2;
    int tofs = wn * 16 + (tg >> 1);
    unsigned xw0[4], xw1[4];
#pragma unroll
    for (int li = 0; li < 4; li++) {
        int local = wm * 32 + (li >> 1) * 16 + (li & 1) * 8 + g;
        uint2 xv = *(const uint2*)&sX[local * 4 + v0];
        xw0[li] = xv.x; xw1[li] = xv.y;
    }

    float sexp[4] = {0, 0, 0, 0}, sdot[4] = {0, 0, 0, 0};

#pragma unroll
    for (int nf = 0; nf < 8; nf++) {
        // B fragments from smem (conflict-free LDS)
        int rloc = wn * 64 + nf * 8 + g;         // local smem row
        unsigned bf[4][2];
#pragma unroll
        for (int kf = 0; kf < 4; kf++) {
            bf[kf][0] = *(const unsigned*)&sWp[rloc * WP_STRIDE + kf * 32 + tg * 4];
            bf[kf][1] = *(const unsigned*)&sWp[rloc * WP_STRIDE + kf * 32 + tg * 4 + 16];
        }

        // d seeded with bp*log2e (replaces zero-init MOVs; bp-add free)
        float2 bpv = *(const float2*)&sBp[wn * 64 + nf * 8 + tg * 2];
        float d[2][4] = {{bpv.x, bpv.y, bpv.x, bpv.y},
                         {bpv.x, bpv.y, bpv.x, bpv.y}};
#pragma unroll
        for (int mf = 0; mf < 2; mf++)
#pragma unroll
            for (int kf = 0; kf < 4; kf++)
                mma16816(d[mf], a[mf][kf], bf[kf]);

        int c0 = n_base + nf * 8 + tg * 2;
        int t  = tofs + nf * 2;                  // bit position in xw words
        if (c0 < NUM_ITEMS) {
#pragma unroll
            for (int mf = 0; mf < 2; mf++)
#pragma unroll
                for (int h = 0; h < 2; h++) {
                    int li = mf * 2 + h;
                    float d0 = d[mf][h * 2 + 0];
                    float d1 = d[mf][h * 2 + 1];
                    sexp[li] += ex2f(d0) + ex2f(d1);
                    if ((xw0[li] >> t) & 1) sdot[li] += d0;
                    if ((xw1[li] >> t) & 1) sdot[li] += d1;
                }
        }
    }

    // reduce sexp/sdot across the 4 threads of each group, atomics per row
#pragma unroll
    for (int li = 0; li < 4; li++) {
        float se = sexp[li], sd = sdot[li];
#pragma unroll
        for (int o = 1; o < 4; o <<= 1) {
            se += __shfl_xor_sync(0xFFFFFFFFu, se, o);
            sd += __shfl_xor_sync(0xFFFFFFFFu, sd, o);
        }
        if (tg == 0) {
            int row = m_base + (li >> 1) * 16 + (li & 1) * 8 + g;
            atomicAdd(&g_sexp[row], se);
            atomicAdd(&g_sdot[row], sd);
        }
    }

    // ---- block-end: scnt via popcount of the x bitmask ----
    if (tid < 128) {
        uint4 wv = *(const uint4*)&sX[tid * 4];
        int cnt = __popc(wv.x) + __popc(wv.y) + __popc(wv.z) + __popc(wv.w);
        if (cnt) atomicAdd(&g_scnt[m_blk + tid], (float)cnt);
    }
}

// ---- 5: final reduction (sdot is in log2e scale -> *LN2) ----
__global__ void k_final(float* __restrict__ out) {
    __shared__ float sm[256];
    float acc = 0.f;
    for (int r = threadIdx.x; r < BATCH; r += 256)
        acc += g_scnt[r] * logf(g_sexp[r]) - g_sdot[r] * LN2;
    sm[threadIdx.x] = acc;
    __syncthreads();
    for (int o = 128; o > 0; o >>= 1) {
        if (threadIdx.x < o) sm[threadIdx.x] += sm[threadIdx.x + o];
        __syncthreads();
    }
    if (threadIdx.x == 0) {
        out[0] = sm[0] / (float)BATCH;
        out[1] = -0.5f * g_kl / (float)BATCH;
    }
}

extern "C" void kernel_launch(void* const* d_in, const int* in_sizes, int n_in,
                              void* d_out, int out_size) {
    const float* graph_vals = (const float*)d_in[0];
    const float* Wq         = (const float*)d_in[1];
    const float* bq         = (const float*)d_in[2];
    const float* Wp         = (const float*)d_in[3];
    const float* bp         = (const float*)d_in[4];
    const float* x          = (const float*)d_in[5];
    const float* eps        = (const float*)d_in[6];
    const int*   graph_rows = (const int*)d_in[7];
    const int*   graph_cols = (const int*)d_in[8];
    const int*   user       = (const int*)d_in[9];
    float* out = (float*)d_out;

    k_prep<<<6763, 256>>>(Wq, Wp, user);
    k_edges<<<(NNZ + 255) / 256, 256>>>(graph_vals, graph_rows, graph_cols, user);
    k_z<<<BATCH, 64>>>(bq, eps, user);
    {
        dim3 grid((NUM_ITEMS + 127) / 128, BATCH / 128);
        k_gemm<<<grid, 256>>>(bp, x);
    }
    k_final<<<1, 256>>>(out);
}